// round 1
// baseline (speedup 1.0000x reference)
#include <cuda_runtime.h>
#include <math.h>

// Problem constants
#define BATCH 4
#define SEQ   2048
#define DIM   1024

// GEMM tiling
#define BM 128
#define BN 128
#define BK 16
#define TM 8
#define TN 8

// Scratch (module-load static allocations; allowed)
__device__ float g_Q[BATCH * SEQ * DIM];
__device__ float g_K[BATCH * SEQ * DIM];
__device__ float g_V[BATCH * SEQ * DIM];
__device__ float g_S[(size_t)BATCH * SEQ * SEQ];

// ---------------------------------------------------------------------------
// Generic tiled SGEMM: C = A * op(B)
//   BT=true : B is [N, K] row-major (C = A * B^T)   -> QKV proj, scores
//   BT=false: B is [K, N] row-major (C = A * B)     -> P*V
// MODE: 0 = plain, 1 = causal-skip (skip blocks fully above diagonal),
//       2 = causal k-limit (k tiles = (by+1)*BM/BK)
// ---------------------------------------------------------------------------
template <bool BT, int MODE>
__global__ __launch_bounds__(256) void gemm_kernel(
    const float* __restrict__ Ag, const float* __restrict__ Bg,
    float* __restrict__ Cg,
    int lda, int ldb, int ldc,
    long strideA, long strideB, long strideC,
    int kTiles)
{
    const int bx = blockIdx.x, by = blockIdx.y, bz = blockIdx.z;
    if (MODE == 1 && bx > by) return;               // fully-masked score block
    if (MODE == 2) kTiles = (by + 1) * (BM / BK);   // only j <= q contributes

    const float* A = Ag + (long)bz * strideA + (long)by * BM * lda;
    const float* B = BT ? (Bg + (long)bz * strideB + (long)bx * BN * ldb)
                        : (Bg + (long)bz * strideB + (long)bx * BN);
    float* C = Cg + (long)bz * strideC + (long)by * BM * ldc + (long)bx * BN;

    __shared__ float As[BK][BM];
    __shared__ float Bs[BK][BN];

    const int tid = threadIdx.x;
    const int tx = tid & 15;       // 0..15
    const int ty = tid >> 4;       // 0..15

    // A (and NT-B) loader: 128x16 tile, each thread 2 x float4
    const int arow = tid >> 2;            // 0..63
    const int acol = (tid & 3) * 4;       // 0,4,8,12
    // NN-B loader: 16x128 tile
    const int brow = tid >> 5;            // 0..7
    const int bcol = (tid & 31) * 4;      // 0..124

    float acc[TM][TN];
    #pragma unroll
    for (int i = 0; i < TM; i++)
        #pragma unroll
        for (int j = 0; j < TN; j++) acc[i][j] = 0.0f;

    for (int kt = 0; kt < kTiles; kt++) {
        // ---- load A tile (transposed into As[k][m]) ----
        {
            const float* Ak = A + kt * BK;
            #pragma unroll
            for (int i = 0; i < 2; i++) {
                int r = arow + i * 64;
                float4 v = *(const float4*)(Ak + (long)r * lda + acol);
                As[acol + 0][r] = v.x;
                As[acol + 1][r] = v.y;
                As[acol + 2][r] = v.z;
                As[acol + 3][r] = v.w;
            }
        }
        // ---- load B tile ----
        if (BT) {
            const float* Bk = B + kt * BK;
            #pragma unroll
            for (int i = 0; i < 2; i++) {
                int r = arow + i * 64;
                float4 v = *(const float4*)(Bk + (long)r * ldb + acol);
                Bs[acol + 0][r] = v.x;
                Bs[acol + 1][r] = v.y;
                Bs[acol + 2][r] = v.z;
                Bs[acol + 3][r] = v.w;
            }
        } else {
            const float* Bk = B + (long)kt * BK * ldb;
            #pragma unroll
            for (int i = 0; i < 2; i++) {
                int r = brow + i * 8;
                float4 v = *(const float4*)(Bk + (long)r * ldb + bcol);
                *(float4*)&Bs[r][bcol] = v;
            }
        }
        __syncthreads();

        // ---- compute ----
        #pragma unroll
        for (int k = 0; k < BK; k++) {
            float ra[TM], rb[TN];
            *(float4*)&ra[0] = *(const float4*)&As[k][ty * TM];
            *(float4*)&ra[4] = *(const float4*)&As[k][ty * TM + 4];
            *(float4*)&rb[0] = *(const float4*)&Bs[k][tx * TN];
            *(float4*)&rb[4] = *(const float4*)&Bs[k][tx * TN + 4];
            #pragma unroll
            for (int i = 0; i < TM; i++)
                #pragma unroll
                for (int j = 0; j < TN; j++)
                    acc[i][j] += ra[i] * rb[j];
        }
        __syncthreads();
    }

    // ---- store ----
    #pragma unroll
    for (int i = 0; i < TM; i++) {
        float* Crow = C + (long)(ty * TM + i) * ldc + tx * TN;
        #pragma unroll
        for (int j = 0; j < TN; j += 4) {
            float4 v = make_float4(acc[i][j], acc[i][j + 1],
                                   acc[i][j + 2], acc[i][j + 3]);
            *(float4*)(Crow + j) = v;
        }
    }
}

// ---------------------------------------------------------------------------
// Row softmax over causal scores.
// Row q reads j in [0, q], writes P[j] = softmax(score/32) for j<=q and
// zero-pads up to the next 128 boundary so the PV GEMM can run dense tiles.
// ---------------------------------------------------------------------------
__global__ __launch_bounds__(256) void softmax_kernel(float* __restrict__ S)
{
    const int q = blockIdx.x;
    const int b = blockIdx.y;
    float* row = S + (long)b * SEQ * SEQ + (long)q * SEQ;
    const int klen = q + 1;
    const int kpad = ((q >> 7) + 1) << 7;   // ceil to 128
    const int tid = threadIdx.x;
    const float scale = 0.03125f;           // 1/sqrt(1024)

    __shared__ float red[8];

    // max
    float m = -1e30f;
    for (int j = tid; j < klen; j += 256) m = fmaxf(m, row[j] * scale);
    #pragma unroll
    for (int o = 16; o > 0; o >>= 1) m = fmaxf(m, __shfl_xor_sync(0xffffffffu, m, o));
    if ((tid & 31) == 0) red[tid >> 5] = m;
    __syncthreads();
    if (tid < 32) {
        float v = (tid < 8) ? red[tid] : -1e30f;
        #pragma unroll
        for (int o = 4; o > 0; o >>= 1) v = fmaxf(v, __shfl_xor_sync(0xffffffffu, v, o));
        if (tid == 0) red[0] = v;
    }
    __syncthreads();
    m = red[0];
    __syncthreads();

    // sum of exp
    float s = 0.0f;
    for (int j = tid; j < klen; j += 256) s += __expf(row[j] * scale - m);
    #pragma unroll
    for (int o = 16; o > 0; o >>= 1) s += __shfl_xor_sync(0xffffffffu, s, o);
    if ((tid & 31) == 0) red[tid >> 5] = s;
    __syncthreads();
    if (tid < 32) {
        float v = (tid < 8) ? red[tid] : 0.0f;
        #pragma unroll
        for (int o = 4; o > 0; o >>= 1) v += __shfl_xor_sync(0xffffffffu, v, o);
        if (tid == 0) red[0] = v;
    }
    __syncthreads();
    const float inv = 1.0f / red[0];

    // write normalized probs + zero-pad to tile boundary
    for (int j = tid; j < klen; j += 256) row[j] = __expf(row[j] * scale - m) * inv;
    for (int j = klen + tid; j < kpad; j += 256) row[j] = 0.0f;
}

// ---------------------------------------------------------------------------
extern "C" void kernel_launch(void* const* d_in, const int* in_sizes, int n_in,
                              void* d_out, int out_size)
{
    const float* x  = (const float*)d_in[0];
    const float* Wq = (const float*)d_in[1];
    const float* Wk = (const float*)d_in[2];
    const float* Wv = (const float*)d_in[3];
    float* out = (float*)d_out;

    float *Q, *K, *V, *S;
    cudaGetSymbolAddress((void**)&Q, g_Q);
    cudaGetSymbolAddress((void**)&K, g_K);
    cudaGetSymbolAddress((void**)&V, g_V);
    cudaGetSymbolAddress((void**)&S, g_S);

    const int kTilesD = DIM / BK;   // 64

    // 1) QKV projections: [8192,1024] @ W^T[1024,1024]
    {
        dim3 grid(DIM / BN, (BATCH * SEQ) / BM, 1);
        gemm_kernel<true, 0><<<grid, 256>>>(x, Wq, Q, DIM, DIM, DIM, 0, 0, 0, kTilesD);
        gemm_kernel<true, 0><<<grid, 256>>>(x, Wk, K, DIM, DIM, DIM, 0, 0, 0, kTilesD);
        gemm_kernel<true, 0><<<grid, 256>>>(x, Wv, V, DIM, DIM, DIM, 0, 0, 0, kTilesD);
    }

    // 2) Scores: per batch, S = Q @ K^T (lower-triangle blocks only)
    {
        dim3 grid(SEQ / BN, SEQ / BM, BATCH);
        gemm_kernel<true, 1><<<grid, 256>>>(
            Q, K, S, DIM, DIM, SEQ,
            (long)SEQ * DIM, (long)SEQ * DIM, (long)SEQ * SEQ, kTilesD);
    }

    // 3) Causal softmax (scale fused)
    {
        dim3 grid(SEQ, BATCH);
        softmax_kernel<<<grid, 256>>>(S);
    }

    // 4) O = P @ V with causal k-limit
    {
        dim3 grid(DIM / BN, SEQ / BM, BATCH);
        gemm_kernel<false, 2><<<grid, 256>>>(
            S, V, out, SEQ, DIM, DIM,
            (long)SEQ * SEQ, (long)SEQ * DIM, (long)SEQ * DIM, 0);
    }
}

// round 8
// speedup vs baseline: 1.0739x; 1.0739x over previous
#include <cuda_runtime.h>
#include <cstdint>
#include <math.h>

#define BATCH 4
#define SEQ   2048
#define DIM   1024

// Scratch (static device allocations; allowed)
__device__ float g_Q[BATCH * SEQ * DIM];
__device__ float g_K[BATCH * SEQ * DIM];
__device__ float g_V[BATCH * SEQ * DIM];
__device__ float g_VT[BATCH * SEQ * DIM];
__device__ float g_S[(size_t)BATCH * SEQ * SEQ];

// ---------------------------------------------------------------------------
__device__ __forceinline__ uint32_t smem_u32(const void* p) {
    uint32_t a;
    asm("{ .reg .u64 t; cvta.to.shared.u64 t, %1; cvt.u32.u64 %0, t; }"
        : "=r"(a) : "l"(p));
    return a;
}
__device__ __forceinline__ void cp_async16(uint32_t dst, const void* src) {
    asm volatile("cp.async.cg.shared.global [%0], [%1], 16;"
                 :: "r"(dst), "l"(src) : "memory");
}
#define CP_COMMIT() asm volatile("cp.async.commit_group;" ::: "memory")
#define CP_WAIT(N)  asm volatile("cp.async.wait_group %0;" :: "n"(N) : "memory")

__device__ __forceinline__ uint32_t f2tf32(float x) {
    uint32_t r;
    asm("cvt.rna.tf32.f32 %0, %1;" : "=r"(r) : "f"(x));
    return r;
}

__device__ __forceinline__ void mma_tf32(float* c, const uint32_t* a, const uint32_t* b) {
    asm volatile(
        "mma.sync.aligned.m16n8k8.row.col.f32.tf32.tf32.f32 "
        "{%0,%1,%2,%3}, {%4,%5,%6,%7}, {%8,%9}, {%0,%1,%2,%3};"
        : "+f"(c[0]), "+f"(c[1]), "+f"(c[2]), "+f"(c[3])
        : "r"(a[0]), "r"(a[1]), "r"(a[2]), "r"(a[3]), "r"(b[0]), "r"(b[1]));
}

// ---------------------------------------------------------------------------
// 3xTF32 mma.sync GEMM, NT form: C[M,N] = A[M,K] * B[N,K]^T
// CTA tile 128x128x32, 8 warps (2x4), warp tile 64x32.
// Each operand split big+small (cvt.rna.tf32); 3 MMAs per fragment pair.
// MODE: 0 plain, 1 causal-skip (scores), 2 causal k-limit (PV)
// ---------------------------------------------------------------------------
#define BK 32
#define APAD 36                       // floats per smem row (32 + 4 pad)
#define TILE_F (128 * APAD)           // floats per tile
#define STAGE_F (2 * TILE_F)          // A + B per stage
#define SMEM_BYTES (2 * STAGE_F * 4)  // 73728

template <int MODE>
__global__ __launch_bounds__(256, 2) void mma_gemm(
    const float* __restrict__ Ag, const float* __restrict__ Bg,
    float* __restrict__ Cg,
    int lda, int ldb, int ldc,
    long strideA, long strideB, long strideC,
    int kTiles)
{
    const int bx = blockIdx.x, by = blockIdx.y, bz = blockIdx.z;
    if (MODE == 1 && bx > by) return;
    if (MODE == 2) kTiles = (by + 1) * 4;   // (by+1)*128 / BK

    extern __shared__ float smem[];
    const int tid = threadIdx.x;
    const int wid = tid >> 5;
    const int lid = tid & 31;
    const int warp_m = wid >> 2;    // 0..1  (64 rows each)
    const int warp_n = wid & 3;     // 0..3  (32 cols each)
    const int g  = lid >> 2;        // 0..7
    const int t4 = lid & 3;         // 0..3

    const float* A = Ag + (long)bz * strideA + (long)by * 128 * lda;
    const float* B = Bg + (long)bz * strideB + (long)bx * 128 * ldb;
    float* C = Cg + (long)bz * strideC + (long)by * 128 * ldc + (long)bx * 128;

    const uint32_t sbase = smem_u32(smem);
    auto stA = [&](int s) { return sbase + (uint32_t)(s * STAGE_F * 4); };
    auto stB = [&](int s) { return sbase + (uint32_t)((s * STAGE_F + TILE_F) * 4); };

    // Loader: 128 rows x 32 floats, 16B chunks; 1024 chunks / 256 thr = 4 each
    auto load_tile = [&](const float* G, int ld, uint32_t dstbase, int kt) {
        const float* src = G + kt * BK;
        #pragma unroll
        for (int i = 0; i < 4; i++) {
            int id  = i * 256 + tid;
            int row = id >> 3;
            int c4  = id & 7;
            cp_async16(dstbase + (uint32_t)(row * APAD + c4 * 4) * 4,
                       src + (long)row * ld + c4 * 4);
        }
    };

    float acc[4][4][4];   // [mt][nt][reg]
    #pragma unroll
    for (int i = 0; i < 4; i++)
        #pragma unroll
        for (int j = 0; j < 4; j++)
            #pragma unroll
            for (int r = 0; r < 4; r++) acc[i][j][r] = 0.0f;

    load_tile(A, lda, stA(0), 0);
    load_tile(B, ldb, stB(0), 0);
    CP_COMMIT();

    for (int kt = 0; kt < kTiles; kt++) {
        const int buf = kt & 1;
        if (kt + 1 < kTiles) {
            load_tile(A, lda, stA(buf ^ 1), kt + 1);
            load_tile(B, ldb, stB(buf ^ 1), kt + 1);
            CP_COMMIT();
            CP_WAIT(1);
        } else {
            CP_WAIT(0);
        }
        __syncthreads();

        const float* As = smem + buf * STAGE_F;
        const float* Bs = smem + buf * STAGE_F + TILE_F;

        #pragma unroll
        for (int kk = 0; kk < 4; kk++) {
            const int k0 = kk * 8;

            // B fragments: split big/small
            uint32_t bfb[4][2], bfs[4][2];
            #pragma unroll
            for (int nt = 0; nt < 4; nt++) {
                const int nb = warp_n * 32 + nt * 8;
                #pragma unroll
                for (int j = 0; j < 2; j++) {
                    float v = Bs[(nb + g) * APAD + k0 + t4 + j * 4];
                    uint32_t big = f2tf32(v);
                    bfb[nt][j] = big;
                    bfs[nt][j] = __float_as_uint(v - __uint_as_float(big));
                }
            }

            #pragma unroll
            for (int mt = 0; mt < 4; mt++) {
                const int rb = warp_m * 64 + mt * 16;
                uint32_t afb[4], afs[4];
                {
                    float v0 = As[(rb + g)     * APAD + k0 + t4];
                    float v1 = As[(rb + g + 8) * APAD + k0 + t4];
                    float v2 = As[(rb + g)     * APAD + k0 + t4 + 4];
                    float v3 = As[(rb + g + 8) * APAD + k0 + t4 + 4];
                    afb[0] = f2tf32(v0); afs[0] = __float_as_uint(v0 - __uint_as_float(afb[0]));
                    afb[1] = f2tf32(v1); afs[1] = __float_as_uint(v1 - __uint_as_float(afb[1]));
                    afb[2] = f2tf32(v2); afs[2] = __float_as_uint(v2 - __uint_as_float(afb[2]));
                    afb[3] = f2tf32(v3); afs[3] = __float_as_uint(v3 - __uint_as_float(afb[3]));
                }
                #pragma unroll
                for (int nt = 0; nt < 4; nt++) {
                    mma_tf32(acc[mt][nt], afs, bfb[nt]);   // small_A * big_B
                    mma_tf32(acc[mt][nt], afb, bfs[nt]);   // big_A * small_B
                    mma_tf32(acc[mt][nt], afb, bfb[nt]);   // big_A * big_B
                }
            }
        }
        __syncthreads();
    }

    // Store: c0,c1 at (row, 2*t4 .. +1); c2,c3 at (row+8, same)
    #pragma unroll
    for (int mt = 0; mt < 4; mt++) {
        const int r0 = warp_m * 64 + mt * 16 + g;
        #pragma unroll
        for (int nt = 0; nt < 4; nt++) {
            const int c0 = warp_n * 32 + nt * 8 + 2 * t4;
            *(float2*)(C + (long)r0 * ldc + c0) =
                make_float2(acc[mt][nt][0], acc[mt][nt][1]);
            *(float2*)(C + (long)(r0 + 8) * ldc + c0) =
                make_float2(acc[mt][nt][2], acc[mt][nt][3]);
        }
    }
}

// ---------------------------------------------------------------------------
// V transpose: per batch [S, D] -> [D, S]
// ---------------------------------------------------------------------------
__global__ __launch_bounds__(256) void transpose_kernel(
    const float* __restrict__ in, float* __restrict__ out)
{
    __shared__ float tile[32][33];
    const int b = blockIdx.z;
    const int s0 = blockIdx.x * 32, d0 = blockIdx.y * 32;
    const float* src = in + (long)b * SEQ * DIM;
    float* dst = out + (long)b * SEQ * DIM;
    const int x = threadIdx.x, y = threadIdx.y;   // 32 x 8
    #pragma unroll
    for (int i = 0; i < 32; i += 8)
        tile[y + i][x] = src[(long)(s0 + y + i) * DIM + d0 + x];
    __syncthreads();
    #pragma unroll
    for (int i = 0; i < 32; i += 8)
        dst[(long)(d0 + y + i) * SEQ + s0 + x] = tile[x][y + i];
}

// ---------------------------------------------------------------------------
// Causal row softmax (scale fused); zero-pads row to next 128 boundary.
// ---------------------------------------------------------------------------
__global__ __launch_bounds__(256) void softmax_kernel(float* __restrict__ S)
{
    const int q = blockIdx.x;
    const int b = blockIdx.y;
    float* row = S + (long)b * SEQ * SEQ + (long)q * SEQ;
    const int klen = q + 1;
    const int kpad = ((q >> 7) + 1) << 7;
    const int tid = threadIdx.x;
    const float scale = 0.03125f;   // 1/sqrt(1024)

    __shared__ float red[8];

    float m = -1e30f;
    for (int j = tid; j < klen; j += 256) m = fmaxf(m, row[j] * scale);
    #pragma unroll
    for (int o = 16; o > 0; o >>= 1) m = fmaxf(m, __shfl_xor_sync(0xffffffffu, m, o));
    if ((tid & 31) == 0) red[tid >> 5] = m;
    __syncthreads();
    if (tid < 32) {
        float v = (tid < 8) ? red[tid] : -1e30f;
        #pragma unroll
        for (int o = 4; o > 0; o >>= 1) v = fmaxf(v, __shfl_xor_sync(0xffffffffu, v, o));
        if (tid == 0) red[0] = v;
    }
    __syncthreads();
    m = red[0];
    __syncthreads();

    float s = 0.0f;
    for (int j = tid; j < klen; j += 256) {
        float e = __expf(row[j] * scale - m);
        row[j] = e;
        s += e;
    }
    #pragma unroll
    for (int o = 16; o > 0; o >>= 1) s += __shfl_xor_sync(0xffffffffu, s, o);
    if ((tid & 31) == 0) red[tid >> 5] = s;
    __syncthreads();
    if (tid < 32) {
        float v = (tid < 8) ? red[tid] : 0.0f;
        #pragma unroll
        for (int o = 4; o > 0; o >>= 1) v += __shfl_xor_sync(0xffffffffu, v, o);
        if (tid == 0) red[0] = v;
    }
    __syncthreads();
    const float inv = 1.0f / red[0];

    for (int j = tid; j < klen; j += 256) row[j] *= inv;
    for (int j = klen + tid; j < kpad; j += 256) row[j] = 0.0f;
}

// ---------------------------------------------------------------------------
extern "C" void kernel_launch(void* const* d_in, const int* in_sizes, int n_in,
                              void* d_out, int out_size)
{
    const float* x  = (const float*)d_in[0];
    const float* Wq = (const float*)d_in[1];
    const float* Wk = (const float*)d_in[2];
    const float* Wv = (const float*)d_in[3];
    float* out = (float*)d_out;

    float *Q, *K, *V, *VT, *S;
    cudaGetSymbolAddress((void**)&Q,  g_Q);
    cudaGetSymbolAddress((void**)&K,  g_K);
    cudaGetSymbolAddress((void**)&V,  g_V);
    cudaGetSymbolAddress((void**)&VT, g_VT);
    cudaGetSymbolAddress((void**)&S,  g_S);

    cudaFuncSetAttribute(mma_gemm<0>, cudaFuncAttributeMaxDynamicSharedMemorySize, SMEM_BYTES);
    cudaFuncSetAttribute(mma_gemm<1>, cudaFuncAttributeMaxDynamicSharedMemorySize, SMEM_BYTES);
    cudaFuncSetAttribute(mma_gemm<2>, cudaFuncAttributeMaxDynamicSharedMemorySize, SMEM_BYTES);

    const int kTilesD = DIM / BK;   // 32

    // 1) QKV projections: [8192,1024] x W[1024,1024]^T
    {
        dim3 grid(DIM / 128, (BATCH * SEQ) / 128, 1);
        mma_gemm<0><<<grid, 256, SMEM_BYTES>>>(x, Wq, Q, DIM, DIM, DIM, 0, 0, 0, kTilesD);
        mma_gemm<0><<<grid, 256, SMEM_BYTES>>>(x, Wk, K, DIM, DIM, DIM, 0, 0, 0, kTilesD);
        mma_gemm<0><<<grid, 256, SMEM_BYTES>>>(x, Wv, V, DIM, DIM, DIM, 0, 0, 0, kTilesD);
    }

    // 2) V transpose (for NT-form PV gemm)
    {
        dim3 grid(SEQ / 32, DIM / 32, BATCH);
        transpose_kernel<<<grid, dim3(32, 8)>>>(V, VT);
    }

    // 3) Scores: S = Q @ K^T, lower-triangle blocks only
    {
        dim3 grid(SEQ / 128, SEQ / 128, BATCH);
        mma_gemm<1><<<grid, 256, SMEM_BYTES>>>(
            Q, K, S, DIM, DIM, SEQ,
            (long)SEQ * DIM, (long)SEQ * DIM, (long)SEQ * SEQ, kTilesD);
    }

    // 4) Causal softmax
    {
        dim3 grid(SEQ, BATCH);
        softmax_kernel<<<grid, 256>>>(S);
    }

    // 5) O = P @ VT^T with causal k-limit
    {
        dim3 grid(DIM / 128, SEQ / 128, BATCH);
        mma_gemm<2><<<grid, 256, SMEM_BYTES>>>(
            S, VT, out, SEQ, SEQ, DIM,
            (long)SEQ * SEQ, (long)SEQ * DIM, (long)SEQ * DIM, 0);
    }
}

// round 12
// speedup vs baseline: 3.3375x; 3.1078x over previous
#include <cuda_runtime.h>
#include <cuda_bf16.h>
#include <cstdint>
#include <math.h>

#define BATCH 4
#define SEQ   2048
#define DIM   1024

typedef __nv_bfloat16 bf16;

// Scratch (static device allocations; allowed)
__device__ bf16  g_xhi[BATCH * SEQ * DIM], g_xlo[BATCH * SEQ * DIM];
__device__ bf16  g_Wqhi[DIM * DIM], g_Wqlo[DIM * DIM];
__device__ bf16  g_Wkhi[DIM * DIM], g_Wklo[DIM * DIM];
__device__ bf16  g_Wvhi[DIM * DIM], g_Wvlo[DIM * DIM];
__device__ bf16  g_Qhi[BATCH * SEQ * DIM], g_Qlo[BATCH * SEQ * DIM];
__device__ bf16  g_Khi[BATCH * SEQ * DIM], g_Klo[BATCH * SEQ * DIM];
__device__ float g_V [BATCH * SEQ * DIM];
__device__ bf16  g_VThi[BATCH * SEQ * DIM], g_VTlo[BATCH * SEQ * DIM];
__device__ float g_S[(size_t)BATCH * SEQ * SEQ];
__device__ bf16  g_Phi[(size_t)BATCH * SEQ * SEQ], g_Plo[(size_t)BATCH * SEQ * SEQ];

// ---------------------------------------------------------------------------
__device__ __forceinline__ uint32_t smem_u32(const void* p) {
    uint32_t a;
    asm("{ .reg .u64 t; cvta.to.shared.u64 t, %1; cvt.u32.u64 %0, t; }"
        : "=r"(a) : "l"(p));
    return a;
}
__device__ __forceinline__ void cp_async16(uint32_t dst, const void* src) {
    asm volatile("cp.async.cg.shared.global [%0], [%1], 16;"
                 :: "r"(dst), "l"(src) : "memory");
}
#define CP_COMMIT() asm volatile("cp.async.commit_group;" ::: "memory")
#define CP_WAIT(N)  asm volatile("cp.async.wait_group %0;" :: "n"(N) : "memory")

__device__ __forceinline__ void ldsm4(uint32_t& r0, uint32_t& r1, uint32_t& r2,
                                      uint32_t& r3, uint32_t addr) {
    asm volatile("ldmatrix.sync.aligned.m8n8.x4.shared.b16 {%0,%1,%2,%3}, [%4];"
                 : "=r"(r0), "=r"(r1), "=r"(r2), "=r"(r3) : "r"(addr));
}

__device__ __forceinline__ void mma_bf16(float* c, const uint32_t* a, const uint32_t* b) {
    asm volatile(
        "mma.sync.aligned.m16n8k16.row.col.f32.bf16.bf16.f32 "
        "{%0,%1,%2,%3}, {%4,%5,%6,%7}, {%8,%9}, {%0,%1,%2,%3};"
        : "+f"(c[0]), "+f"(c[1]), "+f"(c[2]), "+f"(c[3])
        : "r"(a[0]), "r"(a[1]), "r"(a[2]), "r"(a[3]), "r"(b[0]), "r"(b[1]));
}

__device__ __forceinline__ uint32_t pack_bf16(float a, float b) {
    bf16 h0 = __float2bfloat16(a), h1 = __float2bfloat16(b);
    return ((uint32_t)__bfloat16_as_ushort(h1) << 16) | __bfloat16_as_ushort(h0);
}

// Swizzled smem byte offset within one tile (rows of 64B = 4 chunks of 16B)
__device__ __forceinline__ uint32_t swz(int row, int chunk) {
    return (uint32_t)(row * 64 + ((chunk ^ ((row >> 1) & 3)) << 4));
}

// ---------------------------------------------------------------------------
// bf16x3 mma.sync GEMM, NT form: C = (Ahi+Alo) * (Bhi+Blo)^T, 3-term expansion.
// CTA 128x128, BK=32, 8 warps (2x4), warp tile 64x32.
// MODE: 0 = bf16 hi/lo output (projections Q,K)
//       1 = fp32 out, causal-skip (scores)
//       2 = fp32 out, causal k-limit (PV)
//       3 = fp32 out, plain (projection V)
// ---------------------------------------------------------------------------
#define BK 32
#define TILE_B 8192                    // 128 rows x 64B
#define STAGE_B (4 * TILE_B)           // Ahi,Alo,Bhi,Blo
#define SMEM_BYTES (2 * STAGE_B)       // 65536

template <int MODE>
__global__ __launch_bounds__(256, 2) void mma_gemm(
    const bf16* __restrict__ AhiG, const bf16* __restrict__ AloG,
    const bf16* __restrict__ BhiG, const bf16* __restrict__ BloG,
    float* __restrict__ Cf, bf16* __restrict__ ChiG, bf16* __restrict__ CloG,
    int lda, int ldb, int ldc,
    long strideA, long strideB, long strideC,
    int kTiles)
{
    const int bx = blockIdx.x, by = blockIdx.y, bz = blockIdx.z;
    if (MODE == 1 && bx > by) return;
    if (MODE == 2) kTiles = (by + 1) * 4;   // (by+1)*128 / BK

    extern __shared__ char smem[];
    const uint32_t sbase = smem_u32(smem);
    const int tid = threadIdx.x;
    const int wid = tid >> 5;
    const int lid = tid & 31;
    const int warp_m = wid >> 2;    // 0..1
    const int warp_n = wid & 3;     // 0..3
    const int g  = lid >> 2;
    const int t4 = lid & 3;

    const long aoff = (long)bz * strideA + (long)by * 128 * lda;
    const long boff = (long)bz * strideB + (long)bx * 128 * ldb;
    const bf16* Ahi = AhiG + aoff;
    const bf16* Alo = AloG + aoff;
    const bf16* Bhi = BhiG + boff;
    const bf16* Blo = BloG + boff;

    // stage s, operand o: 0=Ahi 1=Alo 2=Bhi 3=Blo
    auto tbase = [&](int s, int o) { return sbase + (uint32_t)(s * STAGE_B + o * TILE_B); };

    // Loader: one operand tile = 128 rows x 4 chunks(16B) = 512 chunks; 2/thread
    auto load_op = [&](const bf16* G, int ld, uint32_t dst, int kt) {
        const bf16* src = G + kt * BK;
        #pragma unroll
        for (int i = 0; i < 2; i++) {
            int id  = i * 256 + tid;
            int row = id >> 2;
            int c   = id & 3;
            cp_async16(dst + swz(row, c), src + (long)row * ld + c * 8);
        }
    };
    auto load_stage = [&](int s, int kt) {
        load_op(Ahi, lda, tbase(s, 0), kt);
        load_op(Alo, lda, tbase(s, 1), kt);
        load_op(Bhi, ldb, tbase(s, 2), kt);
        load_op(Blo, ldb, tbase(s, 3), kt);
    };

    float acc[4][4][4];
    #pragma unroll
    for (int i = 0; i < 4; i++)
        #pragma unroll
        for (int j = 0; j < 4; j++)
            #pragma unroll
            for (int r = 0; r < 4; r++) acc[i][j][r] = 0.0f;

    // ldmatrix lane mapping
    const int mat = lid >> 3;      // 0..3
    const int mrw = lid & 7;       // row within 8x8 matrix
    // A: row = base + (mat&1)*8 + mrw, chunk = kk*2 + (mat>>1)
    const int a_roff = (mat & 1) * 8 + mrw;
    const int a_coff = mat >> 1;
    // B: row = base + (mat>>1)*8 + mrw, chunk = kk*2 + (mat&1)
    const int b_roff = (mat >> 1) * 8 + mrw;
    const int b_coff = mat & 1;

    load_stage(0, 0);
    CP_COMMIT();

    for (int kt = 0; kt < kTiles; kt++) {
        const int buf = kt & 1;
        if (kt + 1 < kTiles) {
            load_stage(buf ^ 1, kt + 1);
            CP_COMMIT();
            CP_WAIT(1);
        } else {
            CP_WAIT(0);
        }
        __syncthreads();

        const uint32_t tAhi = tbase(buf, 0), tAlo = tbase(buf, 1);
        const uint32_t tBhi = tbase(buf, 2), tBlo = tbase(buf, 3);

        #pragma unroll
        for (int kk = 0; kk < 2; kk++) {            // two k16 steps per BK=32
            // B fragments: 2 ldmatrix.x4 per half (each covers 2 nt)
            uint32_t bh[4][2], bl[4][2];
            #pragma unroll
            for (int p = 0; p < 2; p++) {
                const int nb = warp_n * 32 + p * 16 + b_roff;
                const uint32_t off = swz(nb, kk * 2 + b_coff);
                ldsm4(bh[2*p][0], bh[2*p][1], bh[2*p+1][0], bh[2*p+1][1], tBhi + off);
                ldsm4(bl[2*p][0], bl[2*p][1], bl[2*p+1][0], bl[2*p+1][1], tBlo + off);
            }
            #pragma unroll
            for (int mt = 0; mt < 4; mt++) {
                const int rb = warp_m * 64 + mt * 16 + a_roff;
                const uint32_t off = swz(rb, kk * 2 + a_coff);
                uint32_t ah[4], al[4];
                ldsm4(ah[0], ah[1], ah[2], ah[3], tAhi + off);
                ldsm4(al[0], al[1], al[2], al[3], tAlo + off);
                #pragma unroll
                for (int nt = 0; nt < 4; nt++) {
                    mma_bf16(acc[mt][nt], ah, bh[nt]);   // hi*hi
                    mma_bf16(acc[mt][nt], ah, bl[nt]);   // hi*lo
                    mma_bf16(acc[mt][nt], al, bh[nt]);   // lo*hi
                }
            }
        }
        __syncthreads();
    }

    // ---- epilogue ----
    const long coff = (long)bz * strideC + (long)by * 128 * ldc + (long)bx * 128;
    #pragma unroll
    for (int mt = 0; mt < 4; mt++) {
        const int r0 = warp_m * 64 + mt * 16 + g;
        #pragma unroll
        for (int nt = 0; nt < 4; nt++) {
            const int c0 = warp_n * 32 + nt * 8 + 2 * t4;
            float v0 = acc[mt][nt][0], v1 = acc[mt][nt][1];
            float v2 = acc[mt][nt][2], v3 = acc[mt][nt][3];
            if (MODE == 0) {
                bf16* Chi = ChiG + coff;
                bf16* Clo = CloG + coff;
                uint32_t h01 = pack_bf16(v0, v1);
                uint32_t h23 = pack_bf16(v2, v3);
                *(uint32_t*)(Chi + (long)r0 * ldc + c0) = h01;
                *(uint32_t*)(Chi + (long)(r0 + 8) * ldc + c0) = h23;
                bf16 h0 = __ushort_as_bfloat16((uint16_t)(h01 & 0xffff));
                bf16 h1 = __ushort_as_bfloat16((uint16_t)(h01 >> 16));
                bf16 h2 = __ushort_as_bfloat16((uint16_t)(h23 & 0xffff));
                bf16 h3 = __ushort_as_bfloat16((uint16_t)(h23 >> 16));
                *(uint32_t*)(Clo + (long)r0 * ldc + c0) =
                    pack_bf16(v0 - __bfloat162float(h0), v1 - __bfloat162float(h1));
                *(uint32_t*)(Clo + (long)(r0 + 8) * ldc + c0) =
                    pack_bf16(v2 - __bfloat162float(h2), v3 - __bfloat162float(h3));
            } else {
                float* C = Cf + coff;
                *(float2*)(C + (long)r0 * ldc + c0) = make_float2(v0, v1);
                *(float2*)(C + (long)(r0 + 8) * ldc + c0) = make_float2(v2, v3);
            }
        }
    }
}

// ---------------------------------------------------------------------------
// Elementwise fp32 -> bf16 hi/lo split
// ---------------------------------------------------------------------------
__global__ __launch_bounds__(256) void split_kernel(
    const float* __restrict__ in, bf16* __restrict__ hi, bf16* __restrict__ lo, int n)
{
    int i = blockIdx.x * 256 + threadIdx.x;
    if (i < n) {
        float v = in[i];
        bf16 h = __float2bfloat16(v);
        hi[i] = h;
        lo[i] = __float2bfloat16(v - __bfloat162float(h));
    }
}

// ---------------------------------------------------------------------------
// V transpose + split: per batch [S, D] fp32 -> [D, S] bf16 hi/lo
// ---------------------------------------------------------------------------
__global__ __launch_bounds__(256) void transpose_split_kernel(
    const float* __restrict__ in, bf16* __restrict__ hi, bf16* __restrict__ lo)
{
    __shared__ float tile[32][33];
    const int b = blockIdx.z;
    const int s0 = blockIdx.x * 32, d0 = blockIdx.y * 32;
    const float* src = in + (long)b * SEQ * DIM;
    bf16* dsth = hi + (long)b * SEQ * DIM;
    bf16* dstl = lo + (long)b * SEQ * DIM;
    const int x = threadIdx.x, y = threadIdx.y;   // 32 x 8
    #pragma unroll
    for (int i = 0; i < 32; i += 8)
        tile[y + i][x] = src[(long)(s0 + y + i) * DIM + d0 + x];
    __syncthreads();
    #pragma unroll
    for (int i = 0; i < 32; i += 8) {
        float v = tile[x][y + i];
        bf16 h = __float2bfloat16(v);
        long o = (long)(d0 + y + i) * SEQ + s0 + x;
        dsth[o] = h;
        dstl[o] = __float2bfloat16(v - __bfloat162float(h));
    }
}

// ---------------------------------------------------------------------------
// Causal row softmax: reads fp32 S, writes bf16 hi/lo P, zero-pads to 128.
// ---------------------------------------------------------------------------
__global__ __launch_bounds__(256) void softmax_kernel(
    const float* __restrict__ S, bf16* __restrict__ Phi, bf16* __restrict__ Plo)
{
    const int q = blockIdx.x;
    const int b = blockIdx.y;
    const float* row = S + (long)b * SEQ * SEQ + (long)q * SEQ;
    bf16* ph = Phi + (long)b * SEQ * SEQ + (long)q * SEQ;
    bf16* pl = Plo + (long)b * SEQ * SEQ + (long)q * SEQ;
    const int klen = q + 1;
    const int kpad = ((q >> 7) + 1) << 7;
    const int tid = threadIdx.x;
    const float scale = 0.03125f;   // 1/sqrt(1024)

    __shared__ float red[8];

    float m = -1e30f;
    for (int j = tid; j < klen; j += 256) m = fmaxf(m, row[j] * scale);
    #pragma unroll
    for (int o = 16; o > 0; o >>= 1) m = fmaxf(m, __shfl_xor_sync(0xffffffffu, m, o));
    if ((tid & 31) == 0) red[tid >> 5] = m;
    __syncthreads();
    if (tid < 32) {
        float v = (tid < 8) ? red[tid] : -1e30f;
        #pragma unroll
        for (int o = 4; o > 0; o >>= 1) v = fmaxf(v, __shfl_xor_sync(0xffffffffu, v, o));
        if (tid == 0) red[0] = v;
    }
    __syncthreads();
    m = red[0];
    __syncthreads();

    float s = 0.0f;
    for (int j = tid; j < klen; j += 256) s += __expf(row[j] * scale - m);
    #pragma unroll
    for (int o = 16; o > 0; o >>= 1) s += __shfl_xor_sync(0xffffffffu, s, o);
    if ((tid & 31) == 0) red[tid >> 5] = s;
    __syncthreads();
    if (tid < 32) {
        float v = (tid < 8) ? red[tid] : 0.0f;
        #pragma unroll
        for (int o = 4; o > 0; o >>= 1) v += __shfl_xor_sync(0xffffffffu, v, o);
        if (tid == 0) red[0] = v;
    }
    __syncthreads();
    const float inv = 1.0f / red[0];

    for (int j = tid; j < klen; j += 256) {
        float p = __expf(row[j] * scale - m) * inv;
        bf16 h = __float2bfloat16(p);
        ph[j] = h;
        pl[j] = __float2bfloat16(p - __bfloat162float(h));
    }
    for (int j = klen + tid; j < kpad; j += 256) {
        ph[j] = __float2bfloat16(0.0f);
        pl[j] = __float2bfloat16(0.0f);
    }
}

// ---------------------------------------------------------------------------
extern "C" void kernel_launch(void* const* d_in, const int* in_sizes, int n_in,
                              void* d_out, int out_size)
{
    const float* x  = (const float*)d_in[0];
    const float* Wq = (const float*)d_in[1];
    const float* Wk = (const float*)d_in[2];
    const float* Wv = (const float*)d_in[3];
    float* out = (float*)d_out;

    bf16 *xhi, *xlo, *Wqhi, *Wqlo, *Wkhi, *Wklo, *Wvhi, *Wvlo;
    bf16 *Qhi, *Qlo, *Khi, *Klo, *VThi, *VTlo, *Phi, *Plo;
    float *V, *S;
    cudaGetSymbolAddress((void**)&xhi,  g_xhi);  cudaGetSymbolAddress((void**)&xlo,  g_xlo);
    cudaGetSymbolAddress((void**)&Wqhi, g_Wqhi); cudaGetSymbolAddress((void**)&Wqlo, g_Wqlo);
    cudaGetSymbolAddress((void**)&Wkhi, g_Wkhi); cudaGetSymbolAddress((void**)&Wklo, g_Wklo);
    cudaGetSymbolAddress((void**)&Wvhi, g_Wvhi); cudaGetSymbolAddress((void**)&Wvlo, g_Wvlo);
    cudaGetSymbolAddress((void**)&Qhi,  g_Qhi);  cudaGetSymbolAddress((void**)&Qlo,  g_Qlo);
    cudaGetSymbolAddress((void**)&Khi,  g_Khi);  cudaGetSymbolAddress((void**)&Klo,  g_Klo);
    cudaGetSymbolAddress((void**)&V,    g_V);
    cudaGetSymbolAddress((void**)&VThi, g_VThi); cudaGetSymbolAddress((void**)&VTlo, g_VTlo);
    cudaGetSymbolAddress((void**)&S,    g_S);
    cudaGetSymbolAddress((void**)&Phi,  g_Phi);  cudaGetSymbolAddress((void**)&Plo,  g_Plo);

    cudaFuncSetAttribute(mma_gemm<0>, cudaFuncAttributeMaxDynamicSharedMemorySize, SMEM_BYTES);
    cudaFuncSetAttribute(mma_gemm<1>, cudaFuncAttributeMaxDynamicSharedMemorySize, SMEM_BYTES);
    cudaFuncSetAttribute(mma_gemm<2>, cudaFuncAttributeMaxDynamicSharedMemorySize, SMEM_BYTES);
    cudaFuncSetAttribute(mma_gemm<3>, cudaFuncAttributeMaxDynamicSharedMemorySize, SMEM_BYTES);

    // 0) split inputs
    {
        const int nx = BATCH * SEQ * DIM, nw = DIM * DIM;
        split_kernel<<<(nx + 255) / 256, 256>>>(x,  xhi,  xlo,  nx);
        split_kernel<<<(nw + 255) / 256, 256>>>(Wq, Wqhi, Wqlo, nw);
        split_kernel<<<(nw + 255) / 256, 256>>>(Wk, Wkhi, Wklo, nw);
        split_kernel<<<(nw + 255) / 256, 256>>>(Wv, Wvhi, Wvlo, nw);
    }

    const int kTilesD = DIM / BK;   // 32

    // 1) projections
    {
        dim3 grid(DIM / 128, (BATCH * SEQ) / 128, 1);
        mma_gemm<0><<<grid, 256, SMEM_BYTES>>>(xhi, xlo, Wqhi, Wqlo,
            nullptr, Qhi, Qlo, DIM, DIM, DIM, 0, 0, 0, kTilesD);
        mma_gemm<0><<<grid, 256, SMEM_BYTES>>>(xhi, xlo, Wkhi, Wklo,
            nullptr, Khi, Klo, DIM, DIM, DIM, 0, 0, 0, kTilesD);
        mma_gemm<3><<<grid, 256, SMEM_BYTES>>>(xhi, xlo, Wvhi, Wvlo,
            V, nullptr, nullptr, DIM, DIM, DIM, 0, 0, 0, kTilesD);
    }

    // 2) V transpose + split
    {
        dim3 grid(SEQ / 32, DIM / 32, BATCH);
        transpose_split_kernel<<<grid, dim3(32, 8)>>>(V, VThi, VTlo);
    }

    // 3) scores (lower-triangle blocks)
    {
        dim3 grid(SEQ / 128, SEQ / 128, BATCH);
        mma_gemm<1><<<grid, 256, SMEM_BYTES>>>(Qhi, Qlo, Khi, Klo,
            S, nullptr, nullptr, DIM, DIM, SEQ,
            (long)SEQ * DIM, (long)SEQ * DIM, (long)SEQ * SEQ, kTilesD);
    }

    // 4) softmax -> P hi/lo
    {
        dim3 grid(SEQ, BATCH);
        softmax_kernel<<<grid, 256>>>(S, Phi, Plo);
    }

    // 5) O = P @ VT^T with causal k-limit
    {
        dim3 grid(DIM / 128, SEQ / 128, BATCH);
        mma_gemm<2><<<grid, 256, SMEM_BYTES>>>(Phi, Plo, VThi, VTlo,
            out, nullptr, nullptr, SEQ, SEQ, DIM,
            (long)SEQ * SEQ, (long)SEQ * DIM, (long)SEQ * DIM, 0);
    }
}

// round 13
// speedup vs baseline: 3.5120x; 1.0523x over previous
#include <cuda_runtime.h>
#include <cuda_bf16.h>
#include <cstdint>
#include <math.h>

#define BATCH 4
#define SEQ   2048
#define DIM   1024

typedef __nv_bfloat16 bf16;

// Scratch (static device allocations; allowed)
__device__ bf16  g_xhi[BATCH * SEQ * DIM], g_xlo[BATCH * SEQ * DIM];
__device__ bf16  g_Wqhi[DIM * DIM], g_Wqlo[DIM * DIM];
__device__ bf16  g_Wkhi[DIM * DIM], g_Wklo[DIM * DIM];
__device__ bf16  g_Wvhi[DIM * DIM], g_Wvlo[DIM * DIM];
__device__ bf16  g_Qhi[BATCH * SEQ * DIM], g_Qlo[BATCH * SEQ * DIM];
__device__ bf16  g_Khi[BATCH * SEQ * DIM], g_Klo[BATCH * SEQ * DIM];
__device__ bf16  g_Vhi[BATCH * SEQ * DIM], g_Vlo[BATCH * SEQ * DIM];
__device__ bf16  g_VThi[BATCH * SEQ * DIM], g_VTlo[BATCH * SEQ * DIM];
__device__ float g_S[(size_t)BATCH * SEQ * SEQ];
__device__ bf16  g_Phi[(size_t)BATCH * SEQ * SEQ], g_Plo[(size_t)BATCH * SEQ * SEQ];

// ---------------------------------------------------------------------------
__device__ __forceinline__ uint32_t smem_u32(const void* p) {
    uint32_t a;
    asm("{ .reg .u64 t; cvta.to.shared.u64 t, %1; cvt.u32.u64 %0, t; }"
        : "=r"(a) : "l"(p));
    return a;
}
__device__ __forceinline__ void cp_async16(uint32_t dst, const void* src) {
    asm volatile("cp.async.cg.shared.global [%0], [%1], 16;"
                 :: "r"(dst), "l"(src) : "memory");
}
#define CP_COMMIT() asm volatile("cp.async.commit_group;" ::: "memory")
#define CP_WAIT(N)  asm volatile("cp.async.wait_group %0;" :: "n"(N) : "memory")

__device__ __forceinline__ void ldsm4(uint32_t& r0, uint32_t& r1, uint32_t& r2,
                                      uint32_t& r3, uint32_t addr) {
    asm volatile("ldmatrix.sync.aligned.m8n8.x4.shared.b16 {%0,%1,%2,%3}, [%4];"
                 : "=r"(r0), "=r"(r1), "=r"(r2), "=r"(r3) : "r"(addr));
}

__device__ __forceinline__ void mma_bf16(float* c, const uint32_t* a, const uint32_t* b) {
    asm volatile(
        "mma.sync.aligned.m16n8k16.row.col.f32.bf16.bf16.f32 "
        "{%0,%1,%2,%3}, {%4,%5,%6,%7}, {%8,%9}, {%0,%1,%2,%3};"
        : "+f"(c[0]), "+f"(c[1]), "+f"(c[2]), "+f"(c[3])
        : "r"(a[0]), "r"(a[1]), "r"(a[2]), "r"(a[3]), "r"(b[0]), "r"(b[1]));
}

__device__ __forceinline__ uint32_t pack_bf16(float a, float b) {
    bf16 h0 = __float2bfloat16(a), h1 = __float2bfloat16(b);
    return ((uint32_t)__bfloat16_as_ushort(h1) << 16) | __bfloat16_as_ushort(h0);
}

// Swizzled smem byte offset within one tile (rows of 64B = 4 chunks of 16B)
__device__ __forceinline__ uint32_t swz(int row, int chunk) {
    return (uint32_t)(row * 64 + ((chunk ^ ((row >> 1) & 3)) << 4));
}

// ---------------------------------------------------------------------------
// bf16x3 mma.sync GEMM, NT form: C = (Ahi+Alo) * (Bhi+Blo)^T, 3-term expansion.
// CTA 128x128, BK=32, 8 warps (2x4), warp tile 64x32.
// 3-stage cp.async pipeline, prefetch distance 2, one sync per iteration.
// MODE: 0 = bf16 hi/lo output (projections Q,K,V)
//       1 = fp32 out, causal-skip (scores)
//       2 = fp32 out, causal k-limit (PV)
// ---------------------------------------------------------------------------
#define BK 32
#define TILE_B 8192                    // 128 rows x 64B
#define STAGE_B (4 * TILE_B)           // Ahi,Alo,Bhi,Blo = 32KB
#define NSTAGE 3
#define SMEM_BYTES (NSTAGE * STAGE_B)  // 98304

template <int MODE>
__global__ __launch_bounds__(256, 2) void mma_gemm(
    const bf16* __restrict__ AhiG, const bf16* __restrict__ AloG,
    const bf16* __restrict__ BhiG, const bf16* __restrict__ BloG,
    float* __restrict__ Cf, bf16* __restrict__ ChiG, bf16* __restrict__ CloG,
    int lda, int ldb, int ldc,
    long strideA, long strideB, long strideC,
    int kTiles)
{
    const int bx = blockIdx.x, by = blockIdx.y, bz = blockIdx.z;
    if (MODE == 1 && bx > by) return;
    if (MODE == 2) kTiles = (by + 1) * 4;   // (by+1)*128 / BK

    extern __shared__ char smem[];
    const uint32_t sbase = smem_u32(smem);
    const int tid = threadIdx.x;
    const int wid = tid >> 5;
    const int lid = tid & 31;
    const int warp_m = wid >> 2;    // 0..1
    const int warp_n = wid & 3;     // 0..3
    const int g  = lid >> 2;
    const int t4 = lid & 3;

    const long aoff = (long)bz * strideA + (long)by * 128 * lda;
    const long boff = (long)bz * strideB + (long)bx * 128 * ldb;
    const bf16* Ahi = AhiG + aoff;
    const bf16* Alo = AloG + aoff;
    const bf16* Bhi = BhiG + boff;
    const bf16* Blo = BloG + boff;

    // stage s, operand o: 0=Ahi 1=Alo 2=Bhi 3=Blo
    auto tbase = [&](int s, int o) { return sbase + (uint32_t)(s * STAGE_B + o * TILE_B); };

    // Loader: one operand tile = 128 rows x 4 chunks(16B) = 512 chunks; 2/thread
    auto load_op = [&](const bf16* G, int ld, uint32_t dst, int kt) {
        const bf16* src = G + kt * BK;
        #pragma unroll
        for (int i = 0; i < 2; i++) {
            int id  = i * 256 + tid;
            int row = id >> 2;
            int c   = id & 3;
            cp_async16(dst + swz(row, c), src + (long)row * ld + c * 8);
        }
    };
    auto load_stage = [&](int s, int kt) {
        load_op(Ahi, lda, tbase(s, 0), kt);
        load_op(Alo, lda, tbase(s, 1), kt);
        load_op(Bhi, ldb, tbase(s, 2), kt);
        load_op(Blo, ldb, tbase(s, 3), kt);
    };

    float acc[4][4][4];
    #pragma unroll
    for (int i = 0; i < 4; i++)
        #pragma unroll
        for (int j = 0; j < 4; j++)
            #pragma unroll
            for (int r = 0; r < 4; r++) acc[i][j][r] = 0.0f;

    // ldmatrix lane mapping
    const int mat = lid >> 3;      // 0..3
    const int mrw = lid & 7;       // row within 8x8 matrix
    const int a_roff = (mat & 1) * 8 + mrw;
    const int a_coff = mat >> 1;
    const int b_roff = (mat >> 1) * 8 + mrw;
    const int b_coff = mat & 1;

    // Prologue: 2 stages in flight
    load_stage(0, 0);
    CP_COMMIT();
    load_stage(1, 1);   // kTiles >= 4 always
    CP_COMMIT();

    int buf = 0;
    for (int kt = 0; kt < kTiles; kt++) {
        if (kt + 1 < kTiles) { CP_WAIT(1); } else { CP_WAIT(0); }
        __syncthreads();

        const uint32_t tAhi = tbase(buf, 0), tAlo = tbase(buf, 1);
        const uint32_t tBhi = tbase(buf, 2), tBlo = tbase(buf, 3);

        #pragma unroll
        for (int kk = 0; kk < 2; kk++) {            // two k16 steps per BK=32
            uint32_t bh[4][2], bl[4][2];
            #pragma unroll
            for (int p = 0; p < 2; p++) {
                const int nb = warp_n * 32 + p * 16 + b_roff;
                const uint32_t off = swz(nb, kk * 2 + b_coff);
                ldsm4(bh[2*p][0], bh[2*p][1], bh[2*p+1][0], bh[2*p+1][1], tBhi + off);
                ldsm4(bl[2*p][0], bl[2*p][1], bl[2*p+1][0], bl[2*p+1][1], tBlo + off);
            }
            #pragma unroll
            for (int mt = 0; mt < 4; mt++) {
                const int rb = warp_m * 64 + mt * 16 + a_roff;
                const uint32_t off = swz(rb, kk * 2 + a_coff);
                uint32_t ah[4], al[4];
                ldsm4(ah[0], ah[1], ah[2], ah[3], tAhi + off);
                ldsm4(al[0], al[1], al[2], al[3], tAlo + off);
                #pragma unroll
                for (int nt = 0; nt < 4; nt++) {
                    mma_bf16(acc[mt][nt], ah, bh[nt]);   // hi*hi
                    mma_bf16(acc[mt][nt], ah, bl[nt]);   // hi*lo
                    mma_bf16(acc[mt][nt], al, bh[nt]);   // lo*hi
                }
            }
        }

        // Prefetch stage kt+2 into the buffer two ahead (never the one being read)
        if (kt + 2 < kTiles) {
            int nb = buf + 2; if (nb >= NSTAGE) nb -= NSTAGE;
            load_stage(nb, kt + 2);
            CP_COMMIT();
        }
        if (++buf == NSTAGE) buf = 0;
    }

    // ---- epilogue ----
    const long coff = (long)bz * strideC + (long)by * 128 * ldc + (long)bx * 128;
    #pragma unroll
    for (int mt = 0; mt < 4; mt++) {
        const int r0 = warp_m * 64 + mt * 16 + g;
        #pragma unroll
        for (int nt = 0; nt < 4; nt++) {
            const int c0 = warp_n * 32 + nt * 8 + 2 * t4;
            float v0 = acc[mt][nt][0], v1 = acc[mt][nt][1];
            float v2 = acc[mt][nt][2], v3 = acc[mt][nt][3];
            if (MODE == 0) {
                bf16* Chi = ChiG + coff;
                bf16* Clo = CloG + coff;
                uint32_t h01 = pack_bf16(v0, v1);
                uint32_t h23 = pack_bf16(v2, v3);
                *(uint32_t*)(Chi + (long)r0 * ldc + c0) = h01;
                *(uint32_t*)(Chi + (long)(r0 + 8) * ldc + c0) = h23;
                bf16 h0 = __ushort_as_bfloat16((uint16_t)(h01 & 0xffff));
                bf16 h1 = __ushort_as_bfloat16((uint16_t)(h01 >> 16));
                bf16 h2 = __ushort_as_bfloat16((uint16_t)(h23 & 0xffff));
                bf16 h3 = __ushort_as_bfloat16((uint16_t)(h23 >> 16));
                *(uint32_t*)(Clo + (long)r0 * ldc + c0) =
                    pack_bf16(v0 - __bfloat162float(h0), v1 - __bfloat162float(h1));
                *(uint32_t*)(Clo + (long)(r0 + 8) * ldc + c0) =
                    pack_bf16(v2 - __bfloat162float(h2), v3 - __bfloat162float(h3));
            } else {
                float* C = Cf + coff;
                *(float2*)(C + (long)r0 * ldc + c0) = make_float2(v0, v1);
                *(float2*)(C + (long)(r0 + 8) * ldc + c0) = make_float2(v2, v3);
            }
        }
    }
}

// ---------------------------------------------------------------------------
// Elementwise fp32 -> bf16 hi/lo split
// ---------------------------------------------------------------------------
__global__ __launch_bounds__(256) void split_kernel(
    const float* __restrict__ in, bf16* __restrict__ hi, bf16* __restrict__ lo, int n)
{
    int i = blockIdx.x * 256 + threadIdx.x;
    if (i < n) {
        float v = in[i];
        bf16 h = __float2bfloat16(v);
        hi[i] = h;
        lo[i] = __float2bfloat16(v - __bfloat162float(h));
    }
}

// ---------------------------------------------------------------------------
// bf16 hi/lo transpose: per batch [S, D] -> [D, S] (pure permutation)
// ---------------------------------------------------------------------------
__global__ __launch_bounds__(256) void transpose_bf16_kernel(
    const bf16* __restrict__ hi, const bf16* __restrict__ lo,
    bf16* __restrict__ thi, bf16* __restrict__ tlo)
{
    __shared__ bf16 th[32][34], tl[32][34];
    const int b = blockIdx.z;
    const int s0 = blockIdx.x * 32, d0 = blockIdx.y * 32;
    const bf16* srch = hi + (long)b * SEQ * DIM;
    const bf16* srcl = lo + (long)b * SEQ * DIM;
    bf16* dsth = thi + (long)b * SEQ * DIM;
    bf16* dstl = tlo + (long)b * SEQ * DIM;
    const int x = threadIdx.x, y = threadIdx.y;   // 32 x 8
    #pragma unroll
    for (int i = 0; i < 32; i += 8) {
        long o = (long)(s0 + y + i) * DIM + d0 + x;
        th[y + i][x] = srch[o];
        tl[y + i][x] = srcl[o];
    }
    __syncthreads();
    #pragma unroll
    for (int i = 0; i < 32; i += 8) {
        long o = (long)(d0 + y + i) * SEQ + s0 + x;
        dsth[o] = th[x][y + i];
        dstl[o] = tl[x][y + i];
    }
}

// ---------------------------------------------------------------------------
// Causal row softmax, single pass: row held in registers (<=8 elems/thread).
// Reads fp32 S, writes bf16 hi/lo P, zero-pads to next 128 boundary.
// ---------------------------------------------------------------------------
__global__ __launch_bounds__(256) void softmax_kernel(
    const float* __restrict__ S, bf16* __restrict__ Phi, bf16* __restrict__ Plo)
{
    const int q = blockIdx.x;
    const int b = blockIdx.y;
    const float* row = S + (long)b * SEQ * SEQ + (long)q * SEQ;
    bf16* ph = Phi + (long)b * SEQ * SEQ + (long)q * SEQ;
    bf16* pl = Plo + (long)b * SEQ * SEQ + (long)q * SEQ;
    const int klen = q + 1;
    const int kpad = ((q >> 7) + 1) << 7;
    const int tid = threadIdx.x;
    const float scale = 0.03125f;   // 1/sqrt(1024)

    __shared__ float red[8];

    float v[8];
    float m = -1e30f;
    #pragma unroll
    for (int i = 0; i < 8; i++) {
        int j = tid + i * 256;
        v[i] = (j < klen) ? row[j] * scale : -1e30f;
        m = fmaxf(m, v[i]);
    }
    #pragma unroll
    for (int o = 16; o > 0; o >>= 1) m = fmaxf(m, __shfl_xor_sync(0xffffffffu, m, o));
    if ((tid & 31) == 0) red[tid >> 5] = m;
    __syncthreads();
    if (tid < 32) {
        float t = (tid < 8) ? red[tid] : -1e30f;
        #pragma unroll
        for (int o = 4; o > 0; o >>= 1) t = fmaxf(t, __shfl_xor_sync(0xffffffffu, t, o));
        if (tid == 0) red[0] = t;
    }
    __syncthreads();
    m = red[0];
    __syncthreads();

    float s = 0.0f;
    #pragma unroll
    for (int i = 0; i < 8; i++) {
        v[i] = __expf(v[i] - m);    // exp(-1e30-m) == 0 for masked lanes
        s += v[i];
    }
    #pragma unroll
    for (int o = 16; o > 0; o >>= 1) s += __shfl_xor_sync(0xffffffffu, s, o);
    if ((tid & 31) == 0) red[tid >> 5] = s;
    __syncthreads();
    if (tid < 32) {
        float t = (tid < 8) ? red[tid] : 0.0f;
        #pragma unroll
        for (int o = 4; o > 0; o >>= 1) t += __shfl_xor_sync(0xffffffffu, t, o);
        if (tid == 0) red[0] = t;
    }
    __syncthreads();
    const float inv = 1.0f / red[0];

    #pragma unroll
    for (int i = 0; i < 8; i++) {
        int j = tid + i * 256;
        if (j < klen) {
            float p = v[i] * inv;
            bf16 h = __float2bfloat16(p);
            ph[j] = h;
            pl[j] = __float2bfloat16(p - __bfloat162float(h));
        } else if (j < kpad) {
            ph[j] = __float2bfloat16(0.0f);
            pl[j] = __float2bfloat16(0.0f);
        }
    }
}

// ---------------------------------------------------------------------------
extern "C" void kernel_launch(void* const* d_in, const int* in_sizes, int n_in,
                              void* d_out, int out_size)
{
    const float* x  = (const float*)d_in[0];
    const float* Wq = (const float*)d_in[1];
    const float* Wk = (const float*)d_in[2];
    const float* Wv = (const float*)d_in[3];
    float* out = (float*)d_out;

    bf16 *xhi, *xlo, *Wqhi, *Wqlo, *Wkhi, *Wklo, *Wvhi, *Wvlo;
    bf16 *Qhi, *Qlo, *Khi, *Klo, *Vhi, *Vlo, *VThi, *VTlo, *Phi, *Plo;
    float *S;
    cudaGetSymbolAddress((void**)&xhi,  g_xhi);  cudaGetSymbolAddress((void**)&xlo,  g_xlo);
    cudaGetSymbolAddress((void**)&Wqhi, g_Wqhi); cudaGetSymbolAddress((void**)&Wqlo, g_Wqlo);
    cudaGetSymbolAddress((void**)&Wkhi, g_Wkhi); cudaGetSymbolAddress((void**)&Wklo, g_Wklo);
    cudaGetSymbolAddress((void**)&Wvhi, g_Wvhi); cudaGetSymbolAddress((void**)&Wvlo, g_Wvlo);
    cudaGetSymbolAddress((void**)&Qhi,  g_Qhi);  cudaGetSymbolAddress((void**)&Qlo,  g_Qlo);
    cudaGetSymbolAddress((void**)&Khi,  g_Khi);  cudaGetSymbolAddress((void**)&Klo,  g_Klo);
    cudaGetSymbolAddress((void**)&Vhi,  g_Vhi);  cudaGetSymbolAddress((void**)&Vlo,  g_Vlo);
    cudaGetSymbolAddress((void**)&VThi, g_VThi); cudaGetSymbolAddress((void**)&VTlo, g_VTlo);
    cudaGetSymbolAddress((void**)&S,    g_S);
    cudaGetSymbolAddress((void**)&Phi,  g_Phi);  cudaGetSymbolAddress((void**)&Plo,  g_Plo);

    cudaFuncSetAttribute(mma_gemm<0>, cudaFuncAttributeMaxDynamicSharedMemorySize, SMEM_BYTES);
    cudaFuncSetAttribute(mma_gemm<1>, cudaFuncAttributeMaxDynamicSharedMemorySize, SMEM_BYTES);
    cudaFuncSetAttribute(mma_gemm<2>, cudaFuncAttributeMaxDynamicSharedMemorySize, SMEM_BYTES);

    // 0) split inputs
    {
        const int nx = BATCH * SEQ * DIM, nw = DIM * DIM;
        split_kernel<<<(nx + 255) / 256, 256>>>(x,  xhi,  xlo,  nx);
        split_kernel<<<(nw + 255) / 256, 256>>>(Wq, Wqhi, Wqlo, nw);
        split_kernel<<<(nw + 255) / 256, 256>>>(Wk, Wkhi, Wklo, nw);
        split_kernel<<<(nw + 255) / 256, 256>>>(Wv, Wvhi, Wvlo, nw);
    }

    const int kTilesD = DIM / BK;   // 32

    // 1) projections (all emit bf16 hi/lo)
    {
        dim3 grid(DIM / 128, (BATCH * SEQ) / 128, 1);
        mma_gemm<0><<<grid, 256, SMEM_BYTES>>>(xhi, xlo, Wqhi, Wqlo,
            nullptr, Qhi, Qlo, DIM, DIM, DIM, 0, 0, 0, kTilesD);
        mma_gemm<0><<<grid, 256, SMEM_BYTES>>>(xhi, xlo, Wkhi, Wklo,
            nullptr, Khi, Klo, DIM, DIM, DIM, 0, 0, 0, kTilesD);
        mma_gemm<0><<<grid, 256, SMEM_BYTES>>>(xhi, xlo, Wvhi, Wvlo,
            nullptr, Vhi, Vlo, DIM, DIM, DIM, 0, 0, 0, kTilesD);
    }

    // 2) V transpose (bf16 permutation)
    {
        dim3 grid(SEQ / 32, DIM / 32, BATCH);
        transpose_bf16_kernel<<<grid, dim3(32, 8)>>>(Vhi, Vlo, VThi, VTlo);
    }

    // 3) scores (lower-triangle blocks)
    {
        dim3 grid(SEQ / 128, SEQ / 128, BATCH);
        mma_gemm<1><<<grid, 256, SMEM_BYTES>>>(Qhi, Qlo, Khi, Klo,
            S, nullptr, nullptr, DIM, DIM, SEQ,
            (long)SEQ * DIM, (long)SEQ * DIM, (long)SEQ * SEQ, kTilesD);
    }

    // 4) softmax -> P hi/lo (single pass, row in registers)
    {
        dim3 grid(SEQ, BATCH);
        softmax_kernel<<<grid, 256>>>(S, Phi, Plo);
    }

    // 5) O = P @ VT^T with causal k-limit
    {
        dim3 grid(DIM / 128, SEQ / 128, BATCH);
        mma_gemm<2><<<grid, 256, SMEM_BYTES>>>(Phi, Plo, VThi, VTlo,
            out, nullptr, nullptr, SEQ, SEQ, DIM,
            (long)SEQ * SEQ, (long)SEQ * DIM, (long)SEQ * DIM, 0);
    }
}

// round 14
// speedup vs baseline: 3.7243x; 1.0605x over previous
#include <cuda_runtime.h>
#include <cuda_bf16.h>
#include <cstdint>
#include <math.h>

#define BATCH 4
#define SEQ   2048
#define DIM   1024

typedef __nv_bfloat16 bf16;

// Scratch (static device allocations; allowed)
__device__ bf16  g_xhi[BATCH * SEQ * DIM], g_xlo[BATCH * SEQ * DIM];
__device__ bf16  g_Wqhi[DIM * DIM], g_Wqlo[DIM * DIM];
__device__ bf16  g_Wkhi[DIM * DIM], g_Wklo[DIM * DIM];
__device__ bf16  g_Wvhi[DIM * DIM], g_Wvlo[DIM * DIM];
__device__ bf16  g_Qhi[BATCH * SEQ * DIM], g_Qlo[BATCH * SEQ * DIM];
__device__ bf16  g_Khi[BATCH * SEQ * DIM], g_Klo[BATCH * SEQ * DIM];
__device__ bf16  g_Vhi[BATCH * SEQ * DIM], g_Vlo[BATCH * SEQ * DIM];
__device__ bf16  g_VThi[BATCH * SEQ * DIM], g_VTlo[BATCH * SEQ * DIM];
__device__ float g_S[(size_t)BATCH * SEQ * SEQ];
__device__ bf16  g_Phi[(size_t)BATCH * SEQ * SEQ], g_Plo[(size_t)BATCH * SEQ * SEQ];

// ---------------------------------------------------------------------------
__device__ __forceinline__ uint32_t smem_u32(const void* p) {
    uint32_t a;
    asm("{ .reg .u64 t; cvta.to.shared.u64 t, %1; cvt.u32.u64 %0, t; }"
        : "=r"(a) : "l"(p));
    return a;
}
__device__ __forceinline__ void cp_async16(uint32_t dst, const void* src) {
    asm volatile("cp.async.cg.shared.global [%0], [%1], 16;"
                 :: "r"(dst), "l"(src) : "memory");
}
#define CP_COMMIT() asm volatile("cp.async.commit_group;" ::: "memory")
#define CP_WAIT(N)  asm volatile("cp.async.wait_group %0;" :: "n"(N) : "memory")

__device__ __forceinline__ void ldsm4(uint32_t& r0, uint32_t& r1, uint32_t& r2,
                                      uint32_t& r3, uint32_t addr) {
    asm volatile("ldmatrix.sync.aligned.m8n8.x4.shared.b16 {%0,%1,%2,%3}, [%4];"
                 : "=r"(r0), "=r"(r1), "=r"(r2), "=r"(r3) : "r"(addr));
}

__device__ __forceinline__ void mma_bf16(float* c, const uint32_t* a, const uint32_t* b) {
    asm volatile(
        "mma.sync.aligned.m16n8k16.row.col.f32.bf16.bf16.f32 "
        "{%0,%1,%2,%3}, {%4,%5,%6,%7}, {%8,%9}, {%0,%1,%2,%3};"
        : "+f"(c[0]), "+f"(c[1]), "+f"(c[2]), "+f"(c[3])
        : "r"(a[0]), "r"(a[1]), "r"(a[2]), "r"(a[3]), "r"(b[0]), "r"(b[1]));
}

__device__ __forceinline__ uint32_t pack_bf16(float a, float b) {
    bf16 h0 = __float2bfloat16(a), h1 = __float2bfloat16(b);
    return ((uint32_t)__bfloat16_as_ushort(h1) << 16) | __bfloat16_as_ushort(h0);
}

// Swizzled smem byte offset within one tile (rows of 64B = 4 chunks of 16B)
__device__ __forceinline__ uint32_t swz(int row, int chunk) {
    return (uint32_t)(row * 64 + ((chunk ^ ((row >> 1) & 3)) << 4));
}

// ---------------------------------------------------------------------------
// bf16x3 mma.sync GEMM body, NT form: C = (Ahi+Alo)*(Bhi+Blo)^T, 3-term.
// CTA 128x128, BK=32, 8 warps (2x4), warp tile 64x32.
// 3-stage cp.async pipeline, prefetch distance 2, one sync per iteration.
// MODE: 0 = bf16 hi/lo output; 1 = fp32 out (scores); 2 = fp32 out (PV)
// ---------------------------------------------------------------------------
#define BK 32
#define TILE_B 8192
#define STAGE_B (4 * TILE_B)
#define NSTAGE 3
#define SMEM_BYTES (NSTAGE * STAGE_B)  // 98304

template <int MODE>
__device__ __forceinline__ void gemm_body(
    const bf16* __restrict__ AhiG, const bf16* __restrict__ AloG,
    const bf16* __restrict__ BhiG, const bf16* __restrict__ BloG,
    float* __restrict__ Cf, bf16* __restrict__ ChiG, bf16* __restrict__ CloG,
    int lda, int ldb, int ldc,
    long strideA, long strideB, long strideC,
    int kTiles, int bx, int by, int bz)
{
    extern __shared__ char smem[];
    const uint32_t sbase = smem_u32(smem);
    const int tid = threadIdx.x;
    const int wid = tid >> 5;
    const int lid = tid & 31;
    const int warp_m = wid >> 2;
    const int warp_n = wid & 3;
    const int g  = lid >> 2;
    const int t4 = lid & 3;

    const long aoff = (long)bz * strideA + (long)by * 128 * lda;
    const long boff = (long)bz * strideB + (long)bx * 128 * ldb;
    const bf16* Ahi = AhiG + aoff;
    const bf16* Alo = AloG + aoff;
    const bf16* Bhi = BhiG + boff;
    const bf16* Blo = BloG + boff;

    auto tbase = [&](int s, int o) { return sbase + (uint32_t)(s * STAGE_B + o * TILE_B); };

    auto load_op = [&](const bf16* G, int ld, uint32_t dst, int kt) {
        const bf16* src = G + kt * BK;
        #pragma unroll
        for (int i = 0; i < 2; i++) {
            int id  = i * 256 + tid;
            int row = id >> 2;
            int c   = id & 3;
            cp_async16(dst + swz(row, c), src + (long)row * ld + c * 8);
        }
    };
    auto load_stage = [&](int s, int kt) {
        load_op(Ahi, lda, tbase(s, 0), kt);
        load_op(Alo, lda, tbase(s, 1), kt);
        load_op(Bhi, ldb, tbase(s, 2), kt);
        load_op(Blo, ldb, tbase(s, 3), kt);
    };

    float acc[4][4][4];
    #pragma unroll
    for (int i = 0; i < 4; i++)
        #pragma unroll
        for (int j = 0; j < 4; j++)
            #pragma unroll
            for (int r = 0; r < 4; r++) acc[i][j][r] = 0.0f;

    const int mat = lid >> 3;
    const int mrw = lid & 7;
    const int a_roff = (mat & 1) * 8 + mrw;
    const int a_coff = mat >> 1;
    const int b_roff = (mat >> 1) * 8 + mrw;
    const int b_coff = mat & 1;

    load_stage(0, 0);
    CP_COMMIT();
    load_stage(1, 1);   // kTiles >= 4 always
    CP_COMMIT();

    int buf = 0;
    for (int kt = 0; kt < kTiles; kt++) {
        if (kt + 1 < kTiles) { CP_WAIT(1); } else { CP_WAIT(0); }
        __syncthreads();

        const uint32_t tAhi = tbase(buf, 0), tAlo = tbase(buf, 1);
        const uint32_t tBhi = tbase(buf, 2), tBlo = tbase(buf, 3);

        #pragma unroll
        for (int kk = 0; kk < 2; kk++) {
            uint32_t bh[4][2], bl[4][2];
            #pragma unroll
            for (int p = 0; p < 2; p++) {
                const int nb = warp_n * 32 + p * 16 + b_roff;
                const uint32_t off = swz(nb, kk * 2 + b_coff);
                ldsm4(bh[2*p][0], bh[2*p][1], bh[2*p+1][0], bh[2*p+1][1], tBhi + off);
                ldsm4(bl[2*p][0], bl[2*p][1], bl[2*p+1][0], bl[2*p+1][1], tBlo + off);
            }
            #pragma unroll
            for (int mt = 0; mt < 4; mt++) {
                const int rb = warp_m * 64 + mt * 16 + a_roff;
                const uint32_t off = swz(rb, kk * 2 + a_coff);
                uint32_t ah[4], al[4];
                ldsm4(ah[0], ah[1], ah[2], ah[3], tAhi + off);
                ldsm4(al[0], al[1], al[2], al[3], tAlo + off);
                #pragma unroll
                for (int nt = 0; nt < 4; nt++) {
                    mma_bf16(acc[mt][nt], ah, bh[nt]);
                    mma_bf16(acc[mt][nt], ah, bl[nt]);
                    mma_bf16(acc[mt][nt], al, bh[nt]);
                }
            }
        }

        if (kt + 2 < kTiles) {
            int nb = buf + 2; if (nb >= NSTAGE) nb -= NSTAGE;
            load_stage(nb, kt + 2);
            CP_COMMIT();
        }
        if (++buf == NSTAGE) buf = 0;
    }

    const long coff = (long)bz * strideC + (long)by * 128 * ldc + (long)bx * 128;
    #pragma unroll
    for (int mt = 0; mt < 4; mt++) {
        const int r0 = warp_m * 64 + mt * 16 + g;
        #pragma unroll
        for (int nt = 0; nt < 4; nt++) {
            const int c0 = warp_n * 32 + nt * 8 + 2 * t4;
            float v0 = acc[mt][nt][0], v1 = acc[mt][nt][1];
            float v2 = acc[mt][nt][2], v3 = acc[mt][nt][3];
            if (MODE == 0) {
                bf16* Chi = ChiG + coff;
                bf16* Clo = CloG + coff;
                uint32_t h01 = pack_bf16(v0, v1);
                uint32_t h23 = pack_bf16(v2, v3);
                *(uint32_t*)(Chi + (long)r0 * ldc + c0) = h01;
                *(uint32_t*)(Chi + (long)(r0 + 8) * ldc + c0) = h23;
                bf16 h0 = __ushort_as_bfloat16((uint16_t)(h01 & 0xffff));
                bf16 h1 = __ushort_as_bfloat16((uint16_t)(h01 >> 16));
                bf16 h2 = __ushort_as_bfloat16((uint16_t)(h23 & 0xffff));
                bf16 h3 = __ushort_as_bfloat16((uint16_t)(h23 >> 16));
                *(uint32_t*)(Clo + (long)r0 * ldc + c0) =
                    pack_bf16(v0 - __bfloat162float(h0), v1 - __bfloat162float(h1));
                *(uint32_t*)(Clo + (long)(r0 + 8) * ldc + c0) =
                    pack_bf16(v2 - __bfloat162float(h2), v3 - __bfloat162float(h3));
            } else {
                float* C = Cf + coff;
                *(float2*)(C + (long)r0 * ldc + c0) = make_float2(v0, v1);
                *(float2*)(C + (long)(r0 + 8) * ldc + c0) = make_float2(v2, v3);
            }
        }
    }
}

// ---------------------------------------------------------------------------
// Fused QKV projection: grid (DIM/128, BS/128, 3); z selects weight/output.
// ---------------------------------------------------------------------------
struct QKVParams {
    const bf16* bh[3]; const bf16* bl[3];
    bf16* ch[3]; bf16* cl[3];
};

__global__ __launch_bounds__(256, 2) void mma_qkv(
    const bf16* __restrict__ xhi, const bf16* __restrict__ xlo, QKVParams p)
{
    const int z = blockIdx.z;
    gemm_body<0>(xhi, xlo, p.bh[z], p.bl[z], nullptr, p.ch[z], p.cl[z],
                 DIM, DIM, DIM, 0, 0, 0, DIM / BK,
                 blockIdx.x, blockIdx.y, 0);
}

// ---------------------------------------------------------------------------
// Scores: compact triangular grid (136 blocks per batch), grid (136, BATCH).
// ---------------------------------------------------------------------------
__global__ __launch_bounds__(256, 2) void mma_scores(
    const bf16* __restrict__ Qhi, const bf16* __restrict__ Qlo,
    const bf16* __restrict__ Khi, const bf16* __restrict__ Klo,
    float* __restrict__ S)
{
    const int idx = blockIdx.x;
    int by = (int)((__fsqrt_rn(8.0f * idx + 1.0f) - 1.0f) * 0.5f);
    if ((by + 1) * (by + 2) / 2 <= idx) by++;
    if (by * (by + 1) / 2 > idx) by--;
    const int bx = idx - by * (by + 1) / 2;
    gemm_body<1>(Qhi, Qlo, Khi, Klo, S, nullptr, nullptr,
                 DIM, DIM, SEQ,
                 (long)SEQ * DIM, (long)SEQ * DIM, (long)SEQ * SEQ,
                 DIM / BK, bx, by, blockIdx.y);
}

// ---------------------------------------------------------------------------
// PV: heavy-first scheduling (by reversed), causal k-limit.
// ---------------------------------------------------------------------------
__global__ __launch_bounds__(256, 2) void mma_pv(
    const bf16* __restrict__ Phi, const bf16* __restrict__ Plo,
    const bf16* __restrict__ VThi, const bf16* __restrict__ VTlo,
    float* __restrict__ out)
{
    const int by = (int)gridDim.y - 1 - (int)blockIdx.y;   // heavy CTAs first
    gemm_body<2>(Phi, Plo, VThi, VTlo, out, nullptr, nullptr,
                 SEQ, SEQ, DIM,
                 (long)SEQ * SEQ, (long)SEQ * DIM, (long)SEQ * DIM,
                 (by + 1) * 4, blockIdx.x, by, blockIdx.z);
}

// ---------------------------------------------------------------------------
// Fused split: x + Wq + Wk + Wv in one launch.
// ---------------------------------------------------------------------------
#define NX (BATCH * SEQ * DIM)
#define NW (DIM * DIM)

struct SplitParams {
    const float* src[4];
    bf16* hi[4]; bf16* lo[4];
    int n[4];
};

__global__ __launch_bounds__(256) void split_all_kernel(SplitParams p)
{
    int i = blockIdx.x * 256 + threadIdx.x;
    #pragma unroll
    for (int s = 0; s < 4; s++) {
        int j = i;
        if (j < p.n[s]) {
            float v = p.src[s][j];
            bf16 h = __float2bfloat16(v);
            p.hi[s][j] = h;
            p.lo[s][j] = __float2bfloat16(v - __bfloat162float(h));
        }
        i -= p.n[s];
        if (i < 0) return;
    }
}

// ---------------------------------------------------------------------------
// bf16 hi/lo transpose: per batch [S, D] -> [D, S]
// ---------------------------------------------------------------------------
__global__ __launch_bounds__(256) void transpose_bf16_kernel(
    const bf16* __restrict__ hi, const bf16* __restrict__ lo,
    bf16* __restrict__ thi, bf16* __restrict__ tlo)
{
    __shared__ bf16 th[32][34], tl[32][34];
    const int b = blockIdx.z;
    const int s0 = blockIdx.x * 32, d0 = blockIdx.y * 32;
    const bf16* srch = hi + (long)b * SEQ * DIM;
    const bf16* srcl = lo + (long)b * SEQ * DIM;
    bf16* dsth = thi + (long)b * SEQ * DIM;
    bf16* dstl = tlo + (long)b * SEQ * DIM;
    const int x = threadIdx.x, y = threadIdx.y;
    #pragma unroll
    for (int i = 0; i < 32; i += 8) {
        long o = (long)(s0 + y + i) * DIM + d0 + x;
        th[y + i][x] = srch[o];
        tl[y + i][x] = srcl[o];
    }
    __syncthreads();
    #pragma unroll
    for (int i = 0; i < 32; i += 8) {
        long o = (long)(d0 + y + i) * SEQ + s0 + x;
        dsth[o] = th[x][y + i];
        dstl[o] = tl[x][y + i];
    }
}

// ---------------------------------------------------------------------------
// Causal row softmax, single pass: row held in registers (<=8 elems/thread).
// ---------------------------------------------------------------------------
__global__ __launch_bounds__(256) void softmax_kernel(
    const float* __restrict__ S, bf16* __restrict__ Phi, bf16* __restrict__ Plo)
{
    const int q = blockIdx.x;
    const int b = blockIdx.y;
    const float* row = S + (long)b * SEQ * SEQ + (long)q * SEQ;
    bf16* ph = Phi + (long)b * SEQ * SEQ + (long)q * SEQ;
    bf16* pl = Plo + (long)b * SEQ * SEQ + (long)q * SEQ;
    const int klen = q + 1;
    const int kpad = ((q >> 7) + 1) << 7;
    const int tid = threadIdx.x;
    const float scale = 0.03125f;   // 1/sqrt(1024)

    __shared__ float red[8];

    float v[8];
    float m = -1e30f;
    #pragma unroll
    for (int i = 0; i < 8; i++) {
        int j = tid + i * 256;
        v[i] = (j < klen) ? row[j] * scale : -1e30f;
        m = fmaxf(m, v[i]);
    }
    #pragma unroll
    for (int o = 16; o > 0; o >>= 1) m = fmaxf(m, __shfl_xor_sync(0xffffffffu, m, o));
    if ((tid & 31) == 0) red[tid >> 5] = m;
    __syncthreads();
    if (tid < 32) {
        float t = (tid < 8) ? red[tid] : -1e30f;
        #pragma unroll
        for (int o = 4; o > 0; o >>= 1) t = fmaxf(t, __shfl_xor_sync(0xffffffffu, t, o));
        if (tid == 0) red[0] = t;
    }
    __syncthreads();
    m = red[0];
    __syncthreads();

    float s = 0.0f;
    #pragma unroll
    for (int i = 0; i < 8; i++) {
        v[i] = __expf(v[i] - m);
        s += v[i];
    }
    #pragma unroll
    for (int o = 16; o > 0; o >>= 1) s += __shfl_xor_sync(0xffffffffu, s, o);
    if ((tid & 31) == 0) red[tid >> 5] = s;
    __syncthreads();
    if (tid < 32) {
        float t = (tid < 8) ? red[tid] : 0.0f;
        #pragma unroll
        for (int o = 4; o > 0; o >>= 1) t += __shfl_xor_sync(0xffffffffu, t, o);
        if (tid == 0) red[0] = t;
    }
    __syncthreads();
    const float inv = 1.0f / red[0];

    #pragma unroll
    for (int i = 0; i < 8; i++) {
        int j = tid + i * 256;
        if (j < klen) {
            float p = v[i] * inv;
            bf16 h = __float2bfloat16(p);
            ph[j] = h;
            pl[j] = __float2bfloat16(p - __bfloat162float(h));
        } else if (j < kpad) {
            ph[j] = __float2bfloat16(0.0f);
            pl[j] = __float2bfloat16(0.0f);
        }
    }
}

// ---------------------------------------------------------------------------
extern "C" void kernel_launch(void* const* d_in, const int* in_sizes, int n_in,
                              void* d_out, int out_size)
{
    const float* x  = (const float*)d_in[0];
    const float* Wq = (const float*)d_in[1];
    const float* Wk = (const float*)d_in[2];
    const float* Wv = (const float*)d_in[3];
    float* out = (float*)d_out;

    bf16 *xhi, *xlo, *Wqhi, *Wqlo, *Wkhi, *Wklo, *Wvhi, *Wvlo;
    bf16 *Qhi, *Qlo, *Khi, *Klo, *Vhi, *Vlo, *VThi, *VTlo, *Phi, *Plo;
    float *S;
    cudaGetSymbolAddress((void**)&xhi,  g_xhi);  cudaGetSymbolAddress((void**)&xlo,  g_xlo);
    cudaGetSymbolAddress((void**)&Wqhi, g_Wqhi); cudaGetSymbolAddress((void**)&Wqlo, g_Wqlo);
    cudaGetSymbolAddress((void**)&Wkhi, g_Wkhi); cudaGetSymbolAddress((void**)&Wklo, g_Wklo);
    cudaGetSymbolAddress((void**)&Wvhi, g_Wvhi); cudaGetSymbolAddress((void**)&Wvlo, g_Wvlo);
    cudaGetSymbolAddress((void**)&Qhi,  g_Qhi);  cudaGetSymbolAddress((void**)&Qlo,  g_Qlo);
    cudaGetSymbolAddress((void**)&Khi,  g_Khi);  cudaGetSymbolAddress((void**)&Klo,  g_Klo);
    cudaGetSymbolAddress((void**)&Vhi,  g_Vhi);  cudaGetSymbolAddress((void**)&Vlo,  g_Vlo);
    cudaGetSymbolAddress((void**)&VThi, g_VThi); cudaGetSymbolAddress((void**)&VTlo, g_VTlo);
    cudaGetSymbolAddress((void**)&S,    g_S);
    cudaGetSymbolAddress((void**)&Phi,  g_Phi);  cudaGetSymbolAddress((void**)&Plo,  g_Plo);

    cudaFuncSetAttribute(mma_qkv,    cudaFuncAttributeMaxDynamicSharedMemorySize, SMEM_BYTES);
    cudaFuncSetAttribute(mma_scores, cudaFuncAttributeMaxDynamicSharedMemorySize, SMEM_BYTES);
    cudaFuncSetAttribute(mma_pv,     cudaFuncAttributeMaxDynamicSharedMemorySize, SMEM_BYTES);

    // 0) fused splits (x, Wq, Wk, Wv)
    {
        SplitParams sp;
        sp.src[0] = x;  sp.hi[0] = xhi;  sp.lo[0] = xlo;  sp.n[0] = NX;
        sp.src[1] = Wq; sp.hi[1] = Wqhi; sp.lo[1] = Wqlo; sp.n[1] = NW;
        sp.src[2] = Wk; sp.hi[2] = Wkhi; sp.lo[2] = Wklo; sp.n[2] = NW;
        sp.src[3] = Wv; sp.hi[3] = Wvhi; sp.lo[3] = Wvlo; sp.n[3] = NW;
        int total = NX + 3 * NW;
        split_all_kernel<<<(total + 255) / 256, 256>>>(sp);
    }

    // 1) fused QKV projections (one launch, 1536 CTAs)
    {
        QKVParams p;
        p.bh[0] = Wqhi; p.bl[0] = Wqlo; p.ch[0] = Qhi; p.cl[0] = Qlo;
        p.bh[1] = Wkhi; p.bl[1] = Wklo; p.ch[1] = Khi; p.cl[1] = Klo;
        p.bh[2] = Wvhi; p.bl[2] = Wvlo; p.ch[2] = Vhi; p.cl[2] = Vlo;
        dim3 grid(DIM / 128, (BATCH * SEQ) / 128, 3);
        mma_qkv<<<grid, 256, SMEM_BYTES>>>(xhi, xlo, p);
    }

    // 2) V transpose (bf16 permutation)
    {
        dim3 grid(SEQ / 32, DIM / 32, BATCH);
        transpose_bf16_kernel<<<grid, dim3(32, 8)>>>(Vhi, Vlo, VThi, VTlo);
    }

    // 3) scores: compact triangular grid (136 blocks x 4 batches)
    {
        dim3 grid(136, BATCH);
        mma_scores<<<grid, 256, SMEM_BYTES>>>(Qhi, Qlo, Khi, Klo, S);
    }

    // 4) softmax -> P hi/lo
    {
        dim3 grid(SEQ, BATCH);
        softmax_kernel<<<grid, 256>>>(S, Phi, Plo);
    }

    // 5) O = P @ VT^T, heavy-first scheduling
    {
        dim3 grid(DIM / 128, SEQ / 128, BATCH);
        mma_pv<<<grid, 256, SMEM_BYTES>>>(Phi, Plo, VThi, VTlo, out);
    }
}